// round 13
// baseline (speedup 1.0000x reference)
#include <cuda_runtime.h>

// Problem constants (fixed shapes)
#define NB   64
#define NH   1024
#define NS   512
#define TPB  128               // 4 warps = 1 warp per SMSP (no co-warp contention)
#define EPT  8                 // elements per thread (NH / TPB)
#define WST  16                // steps per smem window
#define NWIN (NS / WST)        // 32 windows
#define ROWLEN 1028            // padded smem row (floats), 16B-aligned rows
#define NWARP (TPB / 32)       // 4

#define SBUF_HALF   (WST * ROWLEN)              // 16448 floats per buffer
#define SM_MASK_OFF (2 * SBUF_HALF)             // 32896
#define SM_WRED_OFF (SM_MASK_OFF + NS)          // 33408 (16B aligned)
#define SM_FLOATS   (SM_WRED_OFF + 2 * 8 * 4)   // 2 parities x 8 float4
#define SMEM_BYTES  (SM_FLOATS * 4)             // 133888 B

__device__ __forceinline__ float clip1(float x) {
    return fminf(fmaxf(x, -1.0f), 1.0f);
}

// 3-value block reduction: 4-level warp butterfly (down to mod-2 partials),
// lanes 0/1 of each warp store -> 8 float4 fan-in. 48 SHFLs/SM/step total.
__device__ __forceinline__ void blk_reduce3(
    float pd, float ph, float ps,
    float* wred, int lane, int warp,
    float& dot, float& hh, float& ss)
{
    #pragma unroll
    for (int m = 16; m >= 2; m >>= 1) {
        pd += __shfl_xor_sync(0xffffffffu, pd, m);
        ph += __shfl_xor_sync(0xffffffffu, ph, m);
        ps += __shfl_xor_sync(0xffffffffu, ps, m);
    }
    if (lane < 2)
        ((float4*)wred)[warp * 2 + lane] = make_float4(pd, ph, ps, 0.0f);
    __syncthreads();
    float4 w0 = ((const float4*)wred)[0];
    float4 w1 = ((const float4*)wred)[1];
    float4 w2 = ((const float4*)wred)[2];
    float4 w3 = ((const float4*)wred)[3];
    float4 w4 = ((const float4*)wred)[4];
    float4 w5 = ((const float4*)wred)[5];
    float4 w6 = ((const float4*)wred)[6];
    float4 w7 = ((const float4*)wred)[7];
    dot = ((w0.x + w1.x) + (w2.x + w3.x)) + ((w4.x + w5.x) + (w6.x + w7.x));
    hh  = ((w0.y + w1.y) + (w2.y + w3.y)) + ((w4.y + w5.y) + (w6.y + w7.y));
    ss  = ((w0.z + w1.z) + (w2.z + w3.z)) + ((w4.z + w5.z) + (w6.z + w7.z));
}

extern "C" __global__ void __launch_bounds__(TPB, 1)
orth_scan_kernel(const float* __restrict__ tree,
                 const float* __restrict__ seq,
                 const float* __restrict__ mask,
                 float* __restrict__ out)
{
    extern __shared__ float sm[];
    float* sbuf = sm;                       // [2][WST][ROWLEN]  transposed windows
    float* msm  = sm + SM_MASK_OFF;         // [NS]
    float* wred = sm + SM_WRED_OFF;         // [2][8*4]

    const int tid  = threadIdx.x;
    const int b    = blockIdx.x;
    const int lane = tid & 31;
    const int warp = tid >> 5;

    const float* seqb = seq + (size_t)b * NH * NS;

    // ---- load carry h (thread owns elements 8*tid .. 8*tid+7) ----
    float h[EPT];
    {
        float4 a0 = *(const float4*)(tree + b * NH + 8 * tid);
        float4 a1 = *(const float4*)(tree + b * NH + 8 * tid + 4);
        h[0]=a0.x; h[1]=a0.y; h[2]=a0.z; h[3]=a0.w;
        h[4]=a1.x; h[5]=a1.y; h[6]=a1.z; h[7]=a1.w;
    }

    // ---- mask row -> smem ----
    msm[tid]       = mask[b * NS + tid];
    msm[tid + 128] = mask[b * NS + 128 + tid];
    msm[tid + 256] = mask[b * NS + 256 + tid];
    msm[tid + 384] = mask[b * NS + 384 + tid];

    // Staging geometry: round q covers rows q*32 .. q*32+31; 4 lanes per row
    // (each lane loads 16B = 4 consecutive t values). 32 rounds per window.
    const int srow = tid >> 2;   // 0..31 row-within-round
    const int tc   = tid & 3;    // 0..3 t-chunk

    // ---- stage window 0 into buffer 0 (transposed: sbuf[t][h]) ----
    #pragma unroll
    for (int half = 0; half < 2; half++) {
        float4 v[16];
        #pragma unroll
        for (int j = 0; j < 16; j++) {
            int r = (half * 16 + j) * 32 + srow;
            v[j] = *(const float4*)(seqb + (size_t)r * NS + 4 * tc);
        }
        #pragma unroll
        for (int j = 0; j < 16; j++) {
            int r = (half * 16 + j) * 32 + srow;
            float* d0 = sbuf + (4 * tc) * ROWLEN + r;
            d0[0 * ROWLEN] = v[j].x;
            d0[1 * ROWLEN] = v[j].y;
            d0[2 * ROWLEN] = v[j].z;
            d0[3 * ROWLEN] = v[j].w;
        }
    }
    __syncthreads();

    // ---- initial reduce for step 0 ----
    float s[EPT];
    {
        float4 a0 = *(const float4*)(sbuf + 8 * tid);
        float4 a1 = *(const float4*)(sbuf + 8 * tid + 4);
        s[0]=a0.x; s[1]=a0.y; s[2]=a0.z; s[3]=a0.w;
        s[4]=a1.x; s[5]=a1.y; s[6]=a1.z; s[7]=a1.w;
    }
    float dot, hh, ss;
    {
        float dp[4], hp[4], sp[4];
        #pragma unroll
        for (int j = 0; j < 4; j++) {
            dp[j] = fmaf(h[2*j+1], s[2*j+1], h[2*j] * s[2*j]);
            hp[j] = fmaf(h[2*j+1], h[2*j+1], h[2*j] * h[2*j]);
            sp[j] = fmaf(s[2*j+1], s[2*j+1], s[2*j] * s[2*j]);
        }
        blk_reduce3((dp[0]+dp[1])+(dp[2]+dp[3]),
                    (hp[0]+hp[1])+(hp[2]+hp[3]),
                    (sp[0]+sp[1])+(sp[2]+sp[3]),
                    wred + 8 * 4, lane, warp, dot, hh, ss);   // parity-1 (t = -1)
    }

    // ---- main scan ----
    for (int win = 0; win < NWIN; ++win) {
        float* cb = sbuf + (win & 1) * SBUF_HALF;        // current window buffer
        float* nb = sbuf + ((win & 1) ^ 1) * SBUF_HALF;  // next window buffer
        const bool notlast = (win + 1 < NWIN);
        float4 stg[16];                                   // circular staging regs

        #pragma unroll
        for (int local = 0; local < WST; ++local) {
            const int t = win * WST + local;

            // prefetch s_{t+1}
            float sn[EPT];
            {
                const float* base = (local < WST - 1)
                    ? (cb + (local + 1) * ROWLEN + 8 * tid)
                    : (nb + 8 * tid);
                if (local < WST - 1 || notlast) {
                    float4 a0 = *(const float4*)(base);
                    float4 a1 = *(const float4*)(base + 4);
                    sn[0]=a0.x; sn[1]=a0.y; sn[2]=a0.z; sn[3]=a0.w;
                    sn[4]=a1.x; sn[5]=a1.y; sn[6]=a1.z; sn[7]=a1.w;
                } else {
                    #pragma unroll
                    for (int j = 0; j < EPT; j++) sn[j] = 0.0f;
                }
            }
            const float m = msm[t];

            // cos = dot / max(sqrt(hh*ss), 1e-8) == dot * rsqrt(max(hh*ss, 1e-16))
            const float arg  = fmaxf(hh * ss, 1e-16f);
            const float cosv = dot * rsqrtf(arg);

            // elementwise update: h = clip(h + (s - h*cos)*m)
            #pragma unroll
            for (int j = 0; j < EPT; j++)
                h[j] = clip1(fmaf(m, fmaf(-cosv, h[j], s[j]), h[j]));

            // stage next window. STS rounds {4(L-4)..+3} at locals 4..11,
            // BEFORE the LDG block so the 16-slot circular buffer's WAR is
            // resolved by register scoreboarding.
            if (notlast && local >= 4 && local < 12) {
                #pragma unroll
                for (int k = 0; k < 4; k++) {
                    const int q = 4 * (local - 4) + k;
                    const int r = q * 32 + srow;
                    float* d0 = nb + (4 * tc) * ROWLEN + r;
                    float4 v = stg[q & 15];
                    d0[0 * ROWLEN] = v.x;
                    d0[1 * ROWLEN] = v.y;
                    d0[2 * ROWLEN] = v.z;
                    d0[3 * ROWLEN] = v.w;
                }
            }
            // LDG rounds {4L..4L+3} at locals 0..7 (4-step gap to the STS)
            if (notlast && local < 8) {
                #pragma unroll
                for (int k = 0; k < 4; k++) {
                    const int q = 4 * local + k;
                    const int r = q * 32 + srow;
                    stg[q & 15] = *(const float4*)(
                        seqb + (size_t)r * NS + (size_t)(win + 1) * WST + 4 * tc);
                }
            }

            if (t < NS - 1) {
                // partials for step t+1 (updated h with s_{t+1}); balanced trees
                float dp[4], hp[4], sp[4];
                #pragma unroll
                for (int j = 0; j < 4; j++) {
                    dp[j] = fmaf(h[2*j+1], sn[2*j+1], h[2*j] * sn[2*j]);
                    hp[j] = fmaf(h[2*j+1], h[2*j+1], h[2*j] * h[2*j]);
                    sp[j] = fmaf(sn[2*j+1], sn[2*j+1], sn[2*j] * sn[2*j]);
                }
                // parity-double-buffered cross-warp reduce (kills WAR race)
                blk_reduce3((dp[0]+dp[1])+(dp[2]+dp[3]),
                            (hp[0]+hp[1])+(hp[2]+hp[3]),
                            (sp[0]+sp[1])+(sp[2]+sp[3]),
                            wred + (t & 1) * (8 * 4),
                            lane, warp, dot, hh, ss);
                #pragma unroll
                for (int j = 0; j < EPT; j++) s[j] = sn[j];
            }
        }
    }

    // ---- write final h ----
    *(float4*)(out + b * NH + 8 * tid)     = make_float4(h[0], h[1], h[2], h[3]);
    *(float4*)(out + b * NH + 8 * tid + 4) = make_float4(h[4], h[5], h[6], h[7]);
}

extern "C" void kernel_launch(void* const* d_in, const int* in_sizes, int n_in,
                              void* d_out, int out_size)
{
    const float* tree = nullptr;
    const float* seq  = nullptr;
    const float* mask = nullptr;
    for (int i = 0; i < n_in; i++) {
        if (in_sizes[i] == NB * NH)           tree = (const float*)d_in[i];
        else if (in_sizes[i] == NB * NH * NS) seq  = (const float*)d_in[i];
        else if (in_sizes[i] == NB * NS)      mask = (const float*)d_in[i];
    }
    float* out = (float*)d_out;

    cudaFuncSetAttribute(orth_scan_kernel,
                         cudaFuncAttributeMaxDynamicSharedMemorySize, SMEM_BYTES);
    orth_scan_kernel<<<NB, TPB, SMEM_BYTES>>>(tree, seq, mask, out);
}